// round 10
// baseline (speedup 1.0000x reference)
#include <cuda_runtime.h>

#define HW 4096
#define CHN 256

// ---------------- scratch (static device memory; no allocations) ----------------
__device__ float g_q[4 * CHN * HW];
__device__ float g_k[4 * CHN * HW];
__device__ float g_v[4 * CHN * HW];
__device__ float g_attn[4 * CHN * HW];
// scores for heads 0-2 only (head 3 is fused/flash):
// sizes 4*n^2: 16384, 262144, 4194304 ; offsets 0, 16384, 278528
// total 4472832 floats = 17.9 MB  -> L2-resident on GB300
__device__ float g_S[4472832];
__device__ float g_rsum[5376];   // reciprocal softmax row sums, heads 0-2

__device__ __forceinline__ int s_off(int h) {
    return (h == 0) ? 0 : (h == 1) ? 16384 : 278528;
}

// =====================================================================
// 1) QKV: q/k/v[b,o,hw] = W[o,:] . x[b,:,hw] + bias   (3 fused GEMMs)
// grid (64 hw-tiles, 4 oc-tiles, 4 batch), 256 threads, 64x64 tiles
// =====================================================================
__global__ __launch_bounds__(256) void qkv_kernel(
    const float* __restrict__ x,
    const float* __restrict__ Wq, const float* __restrict__ bq,
    const float* __restrict__ Wk, const float* __restrict__ bk,
    const float* __restrict__ Wv, const float* __restrict__ bv)
{
    __shared__ float Xs[16][68];
    __shared__ float Qw[16][68], Kw[16][68], Vw[16][68];
    const int n0 = blockIdx.x << 6;
    const int o0 = blockIdx.y << 6;
    const int b  = blockIdx.z;
    const float* xb = x + b * CHN * HW;
    const int tid = threadIdx.x;
    const int tx = tid & 15, ty = tid >> 4;
    const int lcol = tid & 63;
    const int lk0  = tid >> 6;
    const int wkk = tid & 15;
    const int wo0 = tid >> 4;

    float aq[4][4] = {{0}}, ak[4][4] = {{0}}, av[4][4] = {{0}};

    for (int k0 = 0; k0 < CHN; k0 += 16) {
        __syncthreads();
        #pragma unroll
        for (int l = 0; l < 4; l++) {
            int kk = lk0 + (l << 2);
            Xs[kk][lcol] = xb[(k0 + kk) * HW + n0 + lcol];
        }
        #pragma unroll
        for (int l = 0; l < 4; l++) {
            int o = wo0 + (l << 4);
            int gi = (o0 + o) * CHN + k0 + wkk;
            Qw[wkk][o] = Wq[gi];
            Kw[wkk][o] = Wk[gi];
            Vw[wkk][o] = Wv[gi];
        }
        __syncthreads();
        #pragma unroll
        for (int kk = 0; kk < 16; kk++) {
            float4 x4 = *(const float4*)&Xs[kk][tx << 2];
            float4 q4 = *(const float4*)&Qw[kk][ty << 2];
            float4 k4 = *(const float4*)&Kw[kk][ty << 2];
            float4 v4 = *(const float4*)&Vw[kk][ty << 2];
            float xr[4] = {x4.x, x4.y, x4.z, x4.w};
            float qr[4] = {q4.x, q4.y, q4.z, q4.w};
            float kr[4] = {k4.x, k4.y, k4.z, k4.w};
            float vr[4] = {v4.x, v4.y, v4.z, v4.w};
            #pragma unroll
            for (int i = 0; i < 4; i++)
                #pragma unroll
                for (int j = 0; j < 4; j++) {
                    aq[i][j] += qr[i] * xr[j];
                    ak[i][j] += kr[i] * xr[j];
                    av[i][j] += vr[i] * xr[j];
                }
        }
    }
    const int base = b * CHN * HW;
    #pragma unroll
    for (int i = 0; i < 4; i++) {
        int oc = o0 + (ty << 2) + i;
        float bqv = bq[oc], bkv = bk[oc], bvv = bv[oc];
        int addr = base + oc * HW + n0 + (tx << 2);
        float4 oq = make_float4(aq[i][0]+bqv, aq[i][1]+bqv, aq[i][2]+bqv, aq[i][3]+bqv);
        float4 ok = make_float4(ak[i][0]+bkv, ak[i][1]+bkv, ak[i][2]+bkv, ak[i][3]+bkv);
        float4 ov = make_float4(av[i][0]+bvv, av[i][1]+bvv, av[i][2]+bvv, av[i][3]+bvv);
        *(float4*)&g_q[addr] = oq;
        *(float4*)&g_k[addr] = ok;
        *(float4*)&g_v[addr] = ov;
    }
}

// =====================================================================
// 2) Scores for heads 0-2: S[b,i,j] = scale * sum_d Qt[i,d]*Kt[j,d]
// block prefix decode; 64x64 output tiles, K-chunks of 16.
// blocks: h0:4, h1:64, h2:1024  -> 1092 total
// =====================================================================
__global__ __launch_bounds__(256) void scores_kernel()
{
    __shared__ float Qs[16][68], Ks[16][68];
    int bx = blockIdx.x;
    int h, local;
    if (bx < 4)          { h = 0; local = bx; }
    else if (bx < 68)    { h = 1; local = bx - 4; }
    else                 { h = 2; local = bx - 68; }

    const int lph = 3 - h, lpw = lph, low = 6 - lpw;
    const int ln = 6 + 2 * h;
    const int lnt = ln - 6;            // log2(n/64)
    const int n = 1 << ln;
    const int co = h << 6;
    const int lppp = lph << 1;
    const int D = 64 << lppp;
    const float scale = 1.0f / (float)(8 << lph);
    const int pppm = (1 << lppp) - 1;
    const int pwm  = (1 << lpw) - 1;
    const int owm  = (1 << low) - 1;

    const int b  = local >> (2 * lnt);
    const int r  = local & ((1 << (2 * lnt)) - 1);
    const int i0 = (r >> lnt) << 6;
    const int j0 = (r & ((1 << lnt) - 1)) << 6;

    float* Sb = g_S + s_off(h) + b * n * n;
    const float* qb = g_q + b * CHN * HW;
    const float* kb = g_k + b * CHN * HW;

    const int tid = threadIdx.x;
    const int tx = tid & 15, ty = tid >> 4;
    const int lcol = tid & 63;
    const int lk0  = tid >> 6;
    const int ti = i0 + lcol;
    const int tj = j0 + lcol;
    const int qi_base = ((ti >> low) << lph) * 64 + ((ti & owm) << lpw);
    const int kj_base = ((tj >> low) << lph) * 64 + ((tj & owm) << lpw);

    float acc[4][4] = {{0}};
    for (int d0 = 0; d0 < D; d0 += 16) {
        __syncthreads();
        #pragma unroll
        for (int l = 0; l < 4; l++) {
            int kk = lk0 + (l << 2);
            int d = d0 + kk;
            int ch = d >> lppp;
            int rem = d & pppm;
            int off = (co + ch) * HW + (rem >> lpw) * 64 + (rem & pwm);
            Qs[kk][lcol] = qb[off + qi_base];
            Ks[kk][lcol] = kb[off + kj_base];
        }
        __syncthreads();
        #pragma unroll
        for (int kk = 0; kk < 16; kk++) {
            float4 a4 = *(const float4*)&Qs[kk][ty << 2];
            float4 b4 = *(const float4*)&Ks[kk][tx << 2];
            float ar[4] = {a4.x, a4.y, a4.z, a4.w};
            float br[4] = {b4.x, b4.y, b4.z, b4.w};
            #pragma unroll
            for (int i = 0; i < 4; i++)
                #pragma unroll
                for (int j = 0; j < 4; j++)
                    acc[i][j] += ar[i] * br[j];
        }
    }
    #pragma unroll
    for (int i = 0; i < 4; i++) {
        float4 o = make_float4(acc[i][0]*scale, acc[i][1]*scale,
                               acc[i][2]*scale, acc[i][3]*scale);
        *(float4*)&Sb[(i0 + (ty << 2) + i) * n + j0 + (tx << 2)] = o;
    }
}

// =====================================================================
// 3) Softmax rows for heads 0-2 (unnormalized exp back; stores 1/rowsum).
// blocks: h0:256, h1:1024, h2:4096 -> 5376 total
// =====================================================================
__global__ __launch_bounds__(256) void softmax_kernel()
{
    int bx = blockIdx.x;
    int h, local;
    if (bx < 256)        { h = 0; local = bx; }
    else if (bx < 1280)  { h = 1; local = bx - 256; }
    else                 { h = 2; local = bx - 1280; }
    const int n = 1 << (6 + 2 * h);
    float* row = g_S + s_off(h) + (long)local * n;

    const int tid = threadIdx.x;
    float vals[4];
    float m = -1e30f;
    #pragma unroll
    for (int l = 0; l < 4; l++) {
        int j = tid + (l << 8);
        vals[l] = (j < n) ? row[j] : -1e30f;
        m = fmaxf(m, vals[l]);
    }
    #pragma unroll
    for (int o = 16; o > 0; o >>= 1) m = fmaxf(m, __shfl_xor_sync(0xffffffffu, m, o));
    __shared__ float red[8];
    if ((tid & 31) == 0) red[tid >> 5] = m;
    __syncthreads();
    float M = red[0];
    #pragma unroll
    for (int w = 1; w < 8; w++) M = fmaxf(M, red[w]);
    __syncthreads();

    float s = 0.f;
    #pragma unroll
    for (int l = 0; l < 4; l++) {
        int j = tid + (l << 8);
        if (j < n) {
            float e = __expf(vals[l] - M);
            row[j] = e;
            s += e;
        }
    }
    #pragma unroll
    for (int o = 16; o > 0; o >>= 1) s += __shfl_xor_sync(0xffffffffu, s, o);
    if ((tid & 31) == 0) red[tid >> 5] = s;
    __syncthreads();
    if (tid == 0) {
        float tot = 0.f;
        #pragma unroll
        for (int w = 0; w < 8; w++) tot += red[w];
        g_rsum[bx] = 1.0f / tot;
    }
}

// =====================================================================
// 4) AV for heads 0-2: Y[i,d] = (1/rowsum_i) * sum_m P[i,m] Vt[m,d]
// 256 blocks per head -> 768 blocks, 64x64 tiles.
// =====================================================================
__global__ __launch_bounds__(256) void av_kernel()
{
    __shared__ float Ps[64][17];
    __shared__ float Vs[16][68];
    const int bx = blockIdx.x;
    const int h = bx >> 8;
    const int local = bx & 255;
    const int lph = 3 - h, lpw = lph, low = 6 - lpw;
    const int ln = 6 + 2 * h;
    const int n = 1 << ln;
    const int co = h << 6;
    const int ldt = lph << 1;          // log2(D/64)
    const int lppp = lph << 1;
    const int pppm = (1 << lppp) - 1;
    const int pwm  = (1 << lpw) - 1;
    const int owm  = (1 << low) - 1;

    const int b  = local >> 6;
    const int r  = local & 63;
    const int i0 = (r >> ldt) << 6;
    const int d0 = (r & ((1 << ldt) - 1)) << 6;

    const int roff = (h == 0) ? 0 : (h == 1) ? 256 : 1280;
    const float* Sb = g_S + s_off(h) + b * n * n;
    const float* vb = g_v + b * CHN * HW;
    float* ob = g_attn + b * CHN * HW;
    const float* rs = g_rsum + roff + b * n;

    const int tid = threadIdx.x;
    const int tx = tid & 15, ty = tid >> 4;
    const int ml = tid & 15;
    const int sl = tid >> 4;

    int choff[4];
    #pragma unroll
    for (int l = 0; l < 4; l++) {
        int dcol = d0 + sl + (l << 4);
        int ch = dcol >> lppp;
        int rem = dcol & pppm;
        choff[l] = (co + ch) * HW + (rem >> lpw) * 64 + (rem & pwm);
    }

    float acc[4][4] = {{0}};
    for (int m0 = 0; m0 < n; m0 += 16) {
        __syncthreads();
        #pragma unroll
        for (int l = 0; l < 4; l++) {
            int i = sl + (l << 4);
            Ps[i][ml] = Sb[(i0 + i) * n + m0 + ml];
        }
        {
            int t = m0 + ml;
            int tb = ((t >> low) << lph) * 64 + ((t & owm) << lpw);
            #pragma unroll
            for (int l = 0; l < 4; l++)
                Vs[ml][sl + (l << 4)] = vb[choff[l] + tb];
        }
        __syncthreads();
        #pragma unroll
        for (int mm = 0; mm < 16; mm++) {
            float4 v4 = *(const float4*)&Vs[mm][tx << 2];
            float vr[4] = {v4.x, v4.y, v4.z, v4.w};
            #pragma unroll
            for (int i = 0; i < 4; i++) {
                float p = Ps[(ty << 2) + i][mm];
                #pragma unroll
                for (int j = 0; j < 4; j++) acc[i][j] += p * vr[j];
            }
        }
    }
    #pragma unroll
    for (int i = 0; i < 4; i++) {
        int tI = i0 + (ty << 2) + i;
        float inv = rs[tI];
        int tb = ((tI >> low) << lph) * 64 + ((tI & owm) << lpw);
        #pragma unroll
        for (int j = 0; j < 4; j++) {
            int dcol = d0 + (tx << 2) + j;
            int ch = dcol >> lppp;
            int rem = dcol & pppm;
            ob[(co + ch) * HW + (rem >> lpw) * 64 + (rem & pwm) + tb] = acc[i][j] * inv;
        }
    }
}

// =====================================================================
// 4b) Head 3 (1x1 patches): fused flash attention, DYNAMIC smem (69.6 KB).
// Tokens = pixels (n=4096), features = channels 192..255 (d=64).
// Q/K/V are [d][token] with token stride 1, channel stride HW.
// One block = 64 query rows; loop over 64-key tiles with online softmax.
// grid 256 = 4 batch x 64 row-tiles, 256 threads, 4x4 micro-tiles.
// =====================================================================
#define F3_STRIDE 68
#define F3_TILE   (64 * F3_STRIDE)
#define F3_SMEM_BYTES (4 * F3_TILE * 4)

__global__ __launch_bounds__(256) void flash3_kernel()
{
    extern __shared__ float fsm[];
    float (*Qs)[F3_STRIDE] = (float(*)[F3_STRIDE])(fsm);               // [d][i], Q pre-scaled
    float (*Ks)[F3_STRIDE] = (float(*)[F3_STRIDE])(fsm + F3_TILE);     // [d][j]
    float (*Vs)[F3_STRIDE] = (float(*)[F3_STRIDE])(fsm + 2 * F3_TILE); // [j][d]
    float (*Ps)[F3_STRIDE] = (float(*)[F3_STRIDE])(fsm + 3 * F3_TILE); // [i][j] / O staging [d][i]

    const int b  = blockIdx.x >> 6;
    const int i0 = (blockIdx.x & 63) << 6;
    const float* qb = g_q + b * CHN * HW + 192 * HW;
    const float* kb = g_k + b * CHN * HW + 192 * HW;
    const float* vb = g_v + b * CHN * HW + 192 * HW;
    float* ob = g_attn + b * CHN * HW + 192 * HW;

    const int tid = threadIdx.x;
    const int tx = tid & 15, ty = tid >> 4;
    const int lcol = tid & 63;
    const int ld0  = tid >> 6;     // 0..3

    // load Q tile once, fold in scale = 1/sqrt(64) = 0.125
    #pragma unroll
    for (int l = 0; l < 16; l++) {
        int d = ld0 + (l << 2);
        Qs[d][lcol] = qb[d * HW + i0 + lcol] * 0.125f;
    }

    float m[4], lsum[4], acc[4][4];
    #pragma unroll
    for (int i = 0; i < 4; i++) {
        m[i] = -1e30f; lsum[i] = 0.f;
        #pragma unroll
        for (int j = 0; j < 4; j++) acc[i][j] = 0.f;
    }

    for (int j0t = 0; j0t < 4096; j0t += 64) {
        __syncthreads();   // protect Ks/Vs/Ps reuse
        #pragma unroll
        for (int l = 0; l < 16; l++) {
            int d = ld0 + (l << 2);
            Ks[d][lcol] = kb[d * HW + j0t + lcol];
            Vs[lcol][d] = vb[d * HW + j0t + lcol];
        }
        __syncthreads();

        // S tile (scaled): s[i][j] = Q[i,:].K[j,:]
        float s[4][4] = {{0}};
        #pragma unroll
        for (int kk = 0; kk < 64; kk++) {
            float4 a4 = *(const float4*)&Qs[kk][ty << 2];
            float4 b4 = *(const float4*)&Ks[kk][tx << 2];
            float ar[4] = {a4.x, a4.y, a4.z, a4.w};
            float br[4] = {b4.x, b4.y, b4.z, b4.w};
            #pragma unroll
            for (int i = 0; i < 4; i++)
                #pragma unroll
                for (int j = 0; j < 4; j++)
                    s[i][j] += ar[i] * br[j];
        }

        // online softmax update (row groups = 16 lanes with same ty)
        #pragma unroll
        for (int i = 0; i < 4; i++) {
            float rm = fmaxf(fmaxf(s[i][0], s[i][1]), fmaxf(s[i][2], s[i][3]));
            #pragma unroll
            for (int o = 8; o > 0; o >>= 1)
                rm = fmaxf(rm, __shfl_xor_sync(0xffffffffu, rm, o));
            float mnew = fmaxf(m[i], rm);
            float c = __expf(m[i] - mnew);
            m[i] = mnew;
            float rs = 0.f;
            #pragma unroll
            for (int j = 0; j < 4; j++) {
                float e = __expf(s[i][j] - mnew);
                s[i][j] = e;
                rs += e;
            }
            #pragma unroll
            for (int o = 8; o > 0; o >>= 1)
                rs += __shfl_xor_sync(0xffffffffu, rs, o);
            lsum[i] = lsum[i] * c + rs;
            #pragma unroll
            for (int j = 0; j < 4; j++) {
                acc[i][j] *= c;
                Ps[(ty << 2) + i][(tx << 2) + j] = s[i][j];
            }
        }
        __syncthreads();

        // O update: acc[i][d] += sum_j P[i][j] * V[j][d]
        #pragma unroll
        for (int jj = 0; jj < 64; jj++) {
            float4 v4 = *(const float4*)&Vs[jj][tx << 2];
            float vr[4] = {v4.x, v4.y, v4.z, v4.w};
            #pragma unroll
            for (int i = 0; i < 4; i++) {
                float p = Ps[(ty << 2) + i][jj];
                #pragma unroll
                for (int j = 0; j < 4; j++) acc[i][j] += p * vr[j];
            }
        }
    }

    // stage O transposed into Ps as [d][i], then write coalesced
    __syncthreads();
    #pragma unroll
    for (int i = 0; i < 4; i++) {
        float inv = 1.0f / lsum[i];
        #pragma unroll
        for (int j = 0; j < 4; j++)
            Ps[(tx << 2) + j][(ty << 2) + i] = acc[i][j] * inv;
    }
    __syncthreads();
    #pragma unroll
    for (int l = 0; l < 16; l++) {
        int d = ld0 + (l << 2);
        ob[d * HW + i0 + lcol] = Ps[d][lcol];
    }
}

// =====================================================================
// 5) 3x3 conv (SAME) + bias + BatchNorm(inference) + LeakyReLU(0.2)
// grid (64 rows, 4 oc-tiles, 4 batch). 64 oc x 64 px per block.
// =====================================================================
__global__ __launch_bounds__(256) void conv_bn_kernel(
    const float* __restrict__ Wo, const float* __restrict__ bo,
    const float* __restrict__ gamma, const float* __restrict__ beta,
    const float* __restrict__ rm, const float* __restrict__ rv,
    float* __restrict__ out)
{
    __shared__ float ins[8][3][66];
    __shared__ float ws[64][72];       // [o][ic*9 + k], ic chunk of 8
    const int hrow = blockIdx.x;
    const int oc0  = blockIdx.y << 6;
    const int b    = blockIdx.z;
    const float* ib = g_attn + b * CHN * HW;
    const int tid = threadIdx.x;
    const int tx = tid & 15, ty = tid >> 4;
    const int px0 = tx << 2;

    float acc[4][4] = {{0}};

    for (int c0 = 0; c0 < CHN; c0 += 8) {
        __syncthreads();
        for (int idx = tid; idx < 8 * 3 * 66; idx += 256) {
            int col = idx % 66;
            int t2  = idx / 66;
            int rr  = t2 % 3;
            int ic  = t2 / 3;
            int grow = hrow + rr - 1;
            int gcol = col - 1;
            float v = 0.f;
            if ((unsigned)grow < 64u && (unsigned)gcol < 64u)
                v = ib[(c0 + ic) * HW + grow * 64 + gcol];
            ins[ic][rr][col] = v;
        }
        for (int idx = tid; idx < 64 * 72; idx += 256) {
            int o  = idx / 72;
            int r2 = idx - o * 72;
            ws[o][r2] = Wo[(oc0 + o) * 2304 + c0 * 9 + r2];
        }
        __syncthreads();
        #pragma unroll
        for (int ic = 0; ic < 8; ic++) {
            #pragma unroll
            for (int ky = 0; ky < 3; ky++) {
                float iv[6];
                #pragma unroll
                for (int u = 0; u < 6; u++) iv[u] = ins[ic][ky][px0 + u];
                #pragma unroll
                for (int kx = 0; kx < 3; kx++) {
                    int kidx = ic * 9 + ky * 3 + kx;
                    float w0 = ws[(ty << 2) + 0][kidx];
                    float w1 = ws[(ty << 2) + 1][kidx];
                    float w2 = ws[(ty << 2) + 2][kidx];
                    float w3 = ws[(ty << 2) + 3][kidx];
                    #pragma unroll
                    for (int j = 0; j < 4; j++) {
                        float xi = iv[j + kx];
                        acc[0][j] += w0 * xi;
                        acc[1][j] += w1 * xi;
                        acc[2][j] += w2 * xi;
                        acc[3][j] += w3 * xi;
                    }
                }
            }
        }
    }
    #pragma unroll
    for (int i = 0; i < 4; i++) {
        int oc = oc0 + (ty << 2) + i;
        float sc = gamma[oc] * rsqrtf(rv[oc] + 1e-5f);
        float sh = beta[oc] - rm[oc] * sc;
        float bov = bo[oc];
        float4 o4;
        float z;
        z = (acc[i][0] + bov) * sc + sh; o4.x = (z >= 0.f) ? z : 0.2f * z;
        z = (acc[i][1] + bov) * sc + sh; o4.y = (z >= 0.f) ? z : 0.2f * z;
        z = (acc[i][2] + bov) * sc + sh; o4.z = (z >= 0.f) ? z : 0.2f * z;
        z = (acc[i][3] + bov) * sc + sh; o4.w = (z >= 0.f) ? z : 0.2f * z;
        *(float4*)&out[b * CHN * HW + oc * HW + hrow * 64 + px0] = o4;
    }
}

// =====================================================================
extern "C" void kernel_launch(void* const* d_in, const int* in_sizes, int n_in,
                              void* d_out, int out_size)
{
    (void)in_sizes; (void)n_in; (void)out_size;
    const float* x   = (const float*)d_in[0];
    const float* Wq  = (const float*)d_in[1];
    const float* bq  = (const float*)d_in[2];
    const float* Wk  = (const float*)d_in[3];
    const float* bk  = (const float*)d_in[4];
    const float* Wv  = (const float*)d_in[5];
    const float* bv  = (const float*)d_in[6];
    const float* Wo  = (const float*)d_in[7];
    const float* bo  = (const float*)d_in[8];
    const float* gm  = (const float*)d_in[9];
    const float* bt  = (const float*)d_in[10];
    const float* rm  = (const float*)d_in[11];
    const float* rv  = (const float*)d_in[12];
    float* out = (float*)d_out;

    // raise dynamic smem cap for flash3 (69,632 B); host attr set, capture-safe
    cudaFuncSetAttribute(flash3_kernel,
                         cudaFuncAttributeMaxDynamicSharedMemorySize,
                         F3_SMEM_BYTES);

    qkv_kernel<<<dim3(64, 4, 4), 256>>>(x, Wq, bq, Wk, bk, Wv, bv);
    flash3_kernel<<<256, 256, F3_SMEM_BYTES>>>();  // head 3 fused
    scores_kernel<<<1092, 256>>>();                // heads 0-2
    softmax_kernel<<<5376, 256>>>();               // heads 0-2
    av_kernel<<<768, 256>>>();                     // heads 0-2
    conv_bn_kernel<<<dim3(64, 4, 4), 256>>>(Wo, bo, gm, bt, rm, rv, out);
}

// round 11
// speedup vs baseline: 1.2542x; 1.2542x over previous
#include <cuda_runtime.h>

#define HW 4096
#define CHN 256

// ---------------- scratch (static device memory; no allocations) ----------------
__device__ float g_q[4 * CHN * HW];
__device__ float g_k[4 * CHN * HW];
__device__ float g_v[4 * CHN * HW];
__device__ float g_attn[4 * CHN * HW];
// scores for heads 0-2 only (head 3 is fused/flash):
// sizes 4*n^2: 16384, 262144, 4194304 ; offsets 0, 16384, 278528
// total 4472832 floats = 17.9 MB  -> L2-resident on GB300
__device__ float g_S[4472832];
__device__ float g_rsum[5376];   // reciprocal softmax row sums, heads 0-2

__device__ __forceinline__ int s_off(int h) {
    return (h == 0) ? 0 : (h == 1) ? 16384 : 278528;
}

// =====================================================================
// 1) QKV: q/k/v[b,o,hw] = W[o,:] . x[b,:,hw] + bias   (3 fused GEMMs)
// grid (64 hw-tiles, 4 oc-tiles, 4 batch), 256 threads, 64x64 tiles
// =====================================================================
__global__ __launch_bounds__(256) void qkv_kernel(
    const float* __restrict__ x,
    const float* __restrict__ Wq, const float* __restrict__ bq,
    const float* __restrict__ Wk, const float* __restrict__ bk,
    const float* __restrict__ Wv, const float* __restrict__ bv)
{
    __shared__ float Xs[16][68];
    __shared__ float Qw[16][68], Kw[16][68], Vw[16][68];
    const int n0 = blockIdx.x << 6;
    const int o0 = blockIdx.y << 6;
    const int b  = blockIdx.z;
    const float* xb = x + b * CHN * HW;
    const int tid = threadIdx.x;
    const int tx = tid & 15, ty = tid >> 4;
    const int lcol = tid & 63;
    const int lk0  = tid >> 6;
    const int wkk = tid & 15;
    const int wo0 = tid >> 4;

    float aq[4][4] = {{0}}, ak[4][4] = {{0}}, av[4][4] = {{0}};

    for (int k0 = 0; k0 < CHN; k0 += 16) {
        __syncthreads();
        #pragma unroll
        for (int l = 0; l < 4; l++) {
            int kk = lk0 + (l << 2);
            Xs[kk][lcol] = xb[(k0 + kk) * HW + n0 + lcol];
        }
        #pragma unroll
        for (int l = 0; l < 4; l++) {
            int o = wo0 + (l << 4);
            int gi = (o0 + o) * CHN + k0 + wkk;
            Qw[wkk][o] = Wq[gi];
            Kw[wkk][o] = Wk[gi];
            Vw[wkk][o] = Wv[gi];
        }
        __syncthreads();
        #pragma unroll
        for (int kk = 0; kk < 16; kk++) {
            float4 x4 = *(const float4*)&Xs[kk][tx << 2];
            float4 q4 = *(const float4*)&Qw[kk][ty << 2];
            float4 k4 = *(const float4*)&Kw[kk][ty << 2];
            float4 v4 = *(const float4*)&Vw[kk][ty << 2];
            float xr[4] = {x4.x, x4.y, x4.z, x4.w};
            float qr[4] = {q4.x, q4.y, q4.z, q4.w};
            float kr[4] = {k4.x, k4.y, k4.z, k4.w};
            float vr[4] = {v4.x, v4.y, v4.z, v4.w};
            #pragma unroll
            for (int i = 0; i < 4; i++)
                #pragma unroll
                for (int j = 0; j < 4; j++) {
                    aq[i][j] += qr[i] * xr[j];
                    ak[i][j] += kr[i] * xr[j];
                    av[i][j] += vr[i] * xr[j];
                }
        }
    }
    const int base = b * CHN * HW;
    #pragma unroll
    for (int i = 0; i < 4; i++) {
        int oc = o0 + (ty << 2) + i;
        float bqv = bq[oc], bkv = bk[oc], bvv = bv[oc];
        int addr = base + oc * HW + n0 + (tx << 2);
        float4 oq = make_float4(aq[i][0]+bqv, aq[i][1]+bqv, aq[i][2]+bqv, aq[i][3]+bqv);
        float4 ok = make_float4(ak[i][0]+bkv, ak[i][1]+bkv, ak[i][2]+bkv, ak[i][3]+bkv);
        float4 ov = make_float4(av[i][0]+bvv, av[i][1]+bvv, av[i][2]+bvv, av[i][3]+bvv);
        *(float4*)&g_q[addr] = oq;
        *(float4*)&g_k[addr] = ok;
        *(float4*)&g_v[addr] = ov;
    }
}

// =====================================================================
// 2) Scores for heads 0-2: S[b,i,j] = scale * sum_d Qt[i,d]*Kt[j,d]
// block prefix decode; 64x64 output tiles, K-chunks of 16.
// blocks: h0:4, h1:64, h2:1024  -> 1092 total
// =====================================================================
__global__ __launch_bounds__(256) void scores_kernel()
{
    __shared__ float Qs[16][68], Ks[16][68];
    int bx = blockIdx.x;
    int h, local;
    if (bx < 4)          { h = 0; local = bx; }
    else if (bx < 68)    { h = 1; local = bx - 4; }
    else                 { h = 2; local = bx - 68; }

    const int lph = 3 - h, lpw = lph, low = 6 - lpw;
    const int ln = 6 + 2 * h;
    const int lnt = ln - 6;            // log2(n/64)
    const int n = 1 << ln;
    const int co = h << 6;
    const int lppp = lph << 1;
    const int D = 64 << lppp;
    const float scale = 1.0f / (float)(8 << lph);
    const int pppm = (1 << lppp) - 1;
    const int pwm  = (1 << lpw) - 1;
    const int owm  = (1 << low) - 1;

    const int b  = local >> (2 * lnt);
    const int r  = local & ((1 << (2 * lnt)) - 1);
    const int i0 = (r >> lnt) << 6;
    const int j0 = (r & ((1 << lnt) - 1)) << 6;

    float* Sb = g_S + s_off(h) + b * n * n;
    const float* qb = g_q + b * CHN * HW;
    const float* kb = g_k + b * CHN * HW;

    const int tid = threadIdx.x;
    const int tx = tid & 15, ty = tid >> 4;
    const int lcol = tid & 63;
    const int lk0  = tid >> 6;
    const int ti = i0 + lcol;
    const int tj = j0 + lcol;
    const int qi_base = ((ti >> low) << lph) * 64 + ((ti & owm) << lpw);
    const int kj_base = ((tj >> low) << lph) * 64 + ((tj & owm) << lpw);

    float acc[4][4] = {{0}};
    for (int d0 = 0; d0 < D; d0 += 16) {
        __syncthreads();
        #pragma unroll
        for (int l = 0; l < 4; l++) {
            int kk = lk0 + (l << 2);
            int d = d0 + kk;
            int ch = d >> lppp;
            int rem = d & pppm;
            int off = (co + ch) * HW + (rem >> lpw) * 64 + (rem & pwm);
            Qs[kk][lcol] = qb[off + qi_base];
            Ks[kk][lcol] = kb[off + kj_base];
        }
        __syncthreads();
        #pragma unroll
        for (int kk = 0; kk < 16; kk++) {
            float4 a4 = *(const float4*)&Qs[kk][ty << 2];
            float4 b4 = *(const float4*)&Ks[kk][tx << 2];
            float ar[4] = {a4.x, a4.y, a4.z, a4.w};
            float br[4] = {b4.x, b4.y, b4.z, b4.w};
            #pragma unroll
            for (int i = 0; i < 4; i++)
                #pragma unroll
                for (int j = 0; j < 4; j++)
                    acc[i][j] += ar[i] * br[j];
        }
    }
    #pragma unroll
    for (int i = 0; i < 4; i++) {
        float4 o = make_float4(acc[i][0]*scale, acc[i][1]*scale,
                               acc[i][2]*scale, acc[i][3]*scale);
        *(float4*)&Sb[(i0 + (ty << 2) + i) * n + j0 + (tx << 2)] = o;
    }
}

// =====================================================================
// 3) Softmax rows for heads 0-2 (unnormalized exp back; stores 1/rowsum).
// blocks: h0:256, h1:1024, h2:4096 -> 5376 total
// =====================================================================
__global__ __launch_bounds__(256) void softmax_kernel()
{
    int bx = blockIdx.x;
    int h, local;
    if (bx < 256)        { h = 0; local = bx; }
    else if (bx < 1280)  { h = 1; local = bx - 256; }
    else                 { h = 2; local = bx - 1280; }
    const int n = 1 << (6 + 2 * h);
    float* row = g_S + s_off(h) + (long)local * n;

    const int tid = threadIdx.x;
    float vals[4];
    float m = -1e30f;
    #pragma unroll
    for (int l = 0; l < 4; l++) {
        int j = tid + (l << 8);
        vals[l] = (j < n) ? row[j] : -1e30f;
        m = fmaxf(m, vals[l]);
    }
    #pragma unroll
    for (int o = 16; o > 0; o >>= 1) m = fmaxf(m, __shfl_xor_sync(0xffffffffu, m, o));
    __shared__ float red[8];
    if ((tid & 31) == 0) red[tid >> 5] = m;
    __syncthreads();
    float M = red[0];
    #pragma unroll
    for (int w = 1; w < 8; w++) M = fmaxf(M, red[w]);
    __syncthreads();

    float s = 0.f;
    #pragma unroll
    for (int l = 0; l < 4; l++) {
        int j = tid + (l << 8);
        if (j < n) {
            float e = __expf(vals[l] - M);
            row[j] = e;
            s += e;
        }
    }
    #pragma unroll
    for (int o = 16; o > 0; o >>= 1) s += __shfl_xor_sync(0xffffffffu, s, o);
    if ((tid & 31) == 0) red[tid >> 5] = s;
    __syncthreads();
    if (tid == 0) {
        float tot = 0.f;
        #pragma unroll
        for (int w = 0; w < 8; w++) tot += red[w];
        g_rsum[bx] = 1.0f / tot;
    }
}

// =====================================================================
// 4) AV for heads 0-2: Y[i,d] = (1/rowsum_i) * sum_m P[i,m] Vt[m,d]
// 256 blocks per head -> 768 blocks, 64x64 tiles.
// =====================================================================
__global__ __launch_bounds__(256) void av_kernel()
{
    __shared__ float Ps[64][17];
    __shared__ float Vs[16][68];
    const int bx = blockIdx.x;
    const int h = bx >> 8;
    const int local = bx & 255;
    const int lph = 3 - h, lpw = lph, low = 6 - lpw;
    const int ln = 6 + 2 * h;
    const int n = 1 << ln;
    const int co = h << 6;
    const int ldt = lph << 1;          // log2(D/64)
    const int lppp = lph << 1;
    const int pppm = (1 << lppp) - 1;
    const int pwm  = (1 << lpw) - 1;
    const int owm  = (1 << low) - 1;

    const int b  = local >> 6;
    const int r  = local & 63;
    const int i0 = (r >> ldt) << 6;
    const int d0 = (r & ((1 << ldt) - 1)) << 6;

    const int roff = (h == 0) ? 0 : (h == 1) ? 256 : 1280;
    const float* Sb = g_S + s_off(h) + b * n * n;
    const float* vb = g_v + b * CHN * HW;
    float* ob = g_attn + b * CHN * HW;
    const float* rs = g_rsum + roff + b * n;

    const int tid = threadIdx.x;
    const int tx = tid & 15, ty = tid >> 4;
    const int ml = tid & 15;
    const int sl = tid >> 4;

    int choff[4];
    #pragma unroll
    for (int l = 0; l < 4; l++) {
        int dcol = d0 + sl + (l << 4);
        int ch = dcol >> lppp;
        int rem = dcol & pppm;
        choff[l] = (co + ch) * HW + (rem >> lpw) * 64 + (rem & pwm);
    }

    float acc[4][4] = {{0}};
    for (int m0 = 0; m0 < n; m0 += 16) {
        __syncthreads();
        #pragma unroll
        for (int l = 0; l < 4; l++) {
            int i = sl + (l << 4);
            Ps[i][ml] = Sb[(i0 + i) * n + m0 + ml];
        }
        {
            int t = m0 + ml;
            int tb = ((t >> low) << lph) * 64 + ((t & owm) << lpw);
            #pragma unroll
            for (int l = 0; l < 4; l++)
                Vs[ml][sl + (l << 4)] = vb[choff[l] + tb];
        }
        __syncthreads();
        #pragma unroll
        for (int mm = 0; mm < 16; mm++) {
            float4 v4 = *(const float4*)&Vs[mm][tx << 2];
            float vr[4] = {v4.x, v4.y, v4.z, v4.w};
            #pragma unroll
            for (int i = 0; i < 4; i++) {
                float p = Ps[(ty << 2) + i][mm];
                #pragma unroll
                for (int j = 0; j < 4; j++) acc[i][j] += p * vr[j];
            }
        }
    }
    #pragma unroll
    for (int i = 0; i < 4; i++) {
        int tI = i0 + (ty << 2) + i;
        float inv = rs[tI];
        int tb = ((tI >> low) << lph) * 64 + ((tI & owm) << lpw);
        #pragma unroll
        for (int j = 0; j < 4; j++) {
            int dcol = d0 + (tx << 2) + j;
            int ch = dcol >> lppp;
            int rem = dcol & pppm;
            ob[(co + ch) * HW + (rem >> lpw) * 64 + (rem & pwm) + tb] = acc[i][j] * inv;
        }
    }
}

// =====================================================================
// 4b) Head 3 (1x1 patches): fused flash attention, DYNAMIC smem (69.6 KB).
// Tokens = pixels (n=4096), features = channels 192..255 (d=64).
// One block = 64 query rows; loop over 64-key tiles with online softmax.
// grid 256 = 4 batch x 64 row-tiles, 256 threads, 4x4 micro-tiles.
// =====================================================================
#define F3_STRIDE 68
#define F3_TILE   (64 * F3_STRIDE)
#define F3_SMEM_BYTES (4 * F3_TILE * 4)

__global__ __launch_bounds__(256) void flash3_kernel()
{
    extern __shared__ float fsm[];
    float (*Qs)[F3_STRIDE] = (float(*)[F3_STRIDE])(fsm);               // [d][i], Q pre-scaled
    float (*Ks)[F3_STRIDE] = (float(*)[F3_STRIDE])(fsm + F3_TILE);     // [d][j]
    float (*Vs)[F3_STRIDE] = (float(*)[F3_STRIDE])(fsm + 2 * F3_TILE); // [j][d]
    float (*Ps)[F3_STRIDE] = (float(*)[F3_STRIDE])(fsm + 3 * F3_TILE); // [i][j] / O staging [d][i]

    const int b  = blockIdx.x >> 6;
    const int i0 = (blockIdx.x & 63) << 6;
    const float* qb = g_q + b * CHN * HW + 192 * HW;
    const float* kb = g_k + b * CHN * HW + 192 * HW;
    const float* vb = g_v + b * CHN * HW + 192 * HW;
    float* ob = g_attn + b * CHN * HW + 192 * HW;

    const int tid = threadIdx.x;
    const int tx = tid & 15, ty = tid >> 4;
    const int lcol = tid & 63;
    const int ld0  = tid >> 6;     // 0..3

    // load Q tile once, fold in scale = 1/sqrt(64) = 0.125
    #pragma unroll
    for (int l = 0; l < 16; l++) {
        int d = ld0 + (l << 2);
        Qs[d][lcol] = qb[d * HW + i0 + lcol] * 0.125f;
    }

    float m[4], lsum[4], acc[4][4];
    #pragma unroll
    for (int i = 0; i < 4; i++) {
        m[i] = -1e30f; lsum[i] = 0.f;
        #pragma unroll
        for (int j = 0; j < 4; j++) acc[i][j] = 0.f;
    }

    for (int j0t = 0; j0t < 4096; j0t += 64) {
        __syncthreads();   // protect Ks/Vs/Ps reuse
        #pragma unroll
        for (int l = 0; l < 16; l++) {
            int d = ld0 + (l << 2);
            Ks[d][lcol] = kb[d * HW + j0t + lcol];
            Vs[lcol][d] = vb[d * HW + j0t + lcol];
        }
        __syncthreads();

        // S tile (scaled): s[i][j] = Q[i,:].K[j,:]
        float s[4][4] = {{0}};
        #pragma unroll
        for (int kk = 0; kk < 64; kk++) {
            float4 a4 = *(const float4*)&Qs[kk][ty << 2];
            float4 b4 = *(const float4*)&Ks[kk][tx << 2];
            float ar[4] = {a4.x, a4.y, a4.z, a4.w};
            float br[4] = {b4.x, b4.y, b4.z, b4.w};
            #pragma unroll
            for (int i = 0; i < 4; i++)
                #pragma unroll
                for (int j = 0; j < 4; j++)
                    s[i][j] += ar[i] * br[j];
        }

        // online softmax update (row groups = 16 lanes with same ty)
        #pragma unroll
        for (int i = 0; i < 4; i++) {
            float rm = fmaxf(fmaxf(s[i][0], s[i][1]), fmaxf(s[i][2], s[i][3]));
            #pragma unroll
            for (int o = 8; o > 0; o >>= 1)
                rm = fmaxf(rm, __shfl_xor_sync(0xffffffffu, rm, o));
            float mnew = fmaxf(m[i], rm);
            float c = __expf(m[i] - mnew);
            m[i] = mnew;
            float rs = 0.f;
            #pragma unroll
            for (int j = 0; j < 4; j++) {
                float e = __expf(s[i][j] - mnew);
                s[i][j] = e;
                rs += e;
            }
            #pragma unroll
            for (int o = 8; o > 0; o >>= 1)
                rs += __shfl_xor_sync(0xffffffffu, rs, o);
            lsum[i] = lsum[i] * c + rs;
            #pragma unroll
            for (int j = 0; j < 4; j++) {
                acc[i][j] *= c;
                Ps[(ty << 2) + i][(tx << 2) + j] = s[i][j];
            }
        }
        __syncthreads();

        // O update: acc[i][d] += sum_j P[i][j] * V[j][d]
        #pragma unroll
        for (int jj = 0; jj < 64; jj++) {
            float4 v4 = *(const float4*)&Vs[jj][tx << 2];
            float vr[4] = {v4.x, v4.y, v4.z, v4.w};
            #pragma unroll
            for (int i = 0; i < 4; i++) {
                float p = Ps[(ty << 2) + i][jj];
                #pragma unroll
                for (int j = 0; j < 4; j++) acc[i][j] += p * vr[j];
            }
        }
    }

    // stage O transposed into Ps as [d][i], then write coalesced
    __syncthreads();
    #pragma unroll
    for (int i = 0; i < 4; i++) {
        float inv = 1.0f / lsum[i];
        #pragma unroll
        for (int j = 0; j < 4; j++)
            Ps[(tx << 2) + j][(ty << 2) + i] = acc[i][j] * inv;
    }
    __syncthreads();
    #pragma unroll
    for (int l = 0; l < 16; l++) {
        int d = ld0 + (l << 2);
        ob[d * HW + i0 + lcol] = Ps[d][lcol];
    }
}

// =====================================================================
// 5) 3x3 conv (SAME) + bias + BatchNorm(inference) + LeakyReLU(0.2)
// TWO output rows per block: grid (32 row-pairs, 4 oc-tiles, 4 batch).
// Weight smem staging amortized over 2x compute vs 1-row version.
// =====================================================================
__global__ __launch_bounds__(256) void conv_bn_kernel(
    const float* __restrict__ Wo, const float* __restrict__ bo,
    const float* __restrict__ gamma, const float* __restrict__ beta,
    const float* __restrict__ rm, const float* __restrict__ rv,
    float* __restrict__ out)
{
    __shared__ float ins[8][4][66];    // 4 input rows: r0-1 .. r0+2
    __shared__ float ws[64][72];       // [o][ic*9 + k], ic chunk of 8
    const int r0   = blockIdx.x << 1;  // first of 2 output rows
    const int oc0  = blockIdx.y << 6;
    const int b    = blockIdx.z;
    const float* ib = g_attn + b * CHN * HW;
    const int tid = threadIdx.x;
    const int tx = tid & 15, ty = tid >> 4;
    const int px0 = tx << 2;

    float acc[2][4][4] = {{{0}}};

    for (int c0 = 0; c0 < CHN; c0 += 8) {
        __syncthreads();
        for (int idx = tid; idx < 8 * 4 * 66; idx += 256) {
            int col = idx % 66;
            int t2  = idx / 66;
            int rr  = t2 & 3;
            int ic  = t2 >> 2;
            int grow = r0 + rr - 1;
            int gcol = col - 1;
            float v = 0.f;
            if ((unsigned)grow < 64u && (unsigned)gcol < 64u)
                v = ib[(c0 + ic) * HW + grow * 64 + gcol];
            ins[ic][rr][col] = v;
        }
        for (int idx = tid; idx < 64 * 72; idx += 256) {
            int o  = idx / 72;
            int r2 = idx - o * 72;
            ws[o][r2] = Wo[(oc0 + o) * 2304 + c0 * 9 + r2];
        }
        __syncthreads();
        #pragma unroll
        for (int ic = 0; ic < 8; ic++) {
            float iv[4][6];
            #pragma unroll
            for (int rr = 0; rr < 4; rr++)
                #pragma unroll
                for (int u = 0; u < 6; u++)
                    iv[rr][u] = ins[ic][rr][px0 + u];
            #pragma unroll
            for (int ky = 0; ky < 3; ky++) {
                #pragma unroll
                for (int kx = 0; kx < 3; kx++) {
                    int kidx = ic * 9 + ky * 3 + kx;
                    float w0 = ws[(ty << 2) + 0][kidx];
                    float w1 = ws[(ty << 2) + 1][kidx];
                    float w2 = ws[(ty << 2) + 2][kidx];
                    float w3 = ws[(ty << 2) + 3][kidx];
                    #pragma unroll
                    for (int j = 0; j < 4; j++) {
                        float x0 = iv[ky][j + kx];       // output row 0
                        float x1 = iv[ky + 1][j + kx];   // output row 1
                        acc[0][0][j] += w0 * x0;  acc[1][0][j] += w0 * x1;
                        acc[0][1][j] += w1 * x0;  acc[1][1][j] += w1 * x1;
                        acc[0][2][j] += w2 * x0;  acc[1][2][j] += w2 * x1;
                        acc[0][3][j] += w3 * x0;  acc[1][3][j] += w3 * x1;
                    }
                }
            }
        }
    }
    #pragma unroll
    for (int i = 0; i < 4; i++) {
        int oc = oc0 + (ty << 2) + i;
        float sc = gamma[oc] * rsqrtf(rv[oc] + 1e-5f);
        float sh = beta[oc] - rm[oc] * sc;
        float bov = bo[oc];
        #pragma unroll
        for (int r = 0; r < 2; r++) {
            float4 o4;
            float z;
            z = (acc[r][i][0] + bov) * sc + sh; o4.x = (z >= 0.f) ? z : 0.2f * z;
            z = (acc[r][i][1] + bov) * sc + sh; o4.y = (z >= 0.f) ? z : 0.2f * z;
            z = (acc[r][i][2] + bov) * sc + sh; o4.z = (z >= 0.f) ? z : 0.2f * z;
            z = (acc[r][i][3] + bov) * sc + sh; o4.w = (z >= 0.f) ? z : 0.2f * z;
            *(float4*)&out[b * CHN * HW + oc * HW + (r0 + r) * 64 + px0] = o4;
        }
    }
}

// =====================================================================
extern "C" void kernel_launch(void* const* d_in, const int* in_sizes, int n_in,
                              void* d_out, int out_size)
{
    (void)in_sizes; (void)n_in; (void)out_size;
    const float* x   = (const float*)d_in[0];
    const float* Wq  = (const float*)d_in[1];
    const float* bq  = (const float*)d_in[2];
    const float* Wk  = (const float*)d_in[3];
    const float* bk  = (const float*)d_in[4];
    const float* Wv  = (const float*)d_in[5];
    const float* bv  = (const float*)d_in[6];
    const float* Wo  = (const float*)d_in[7];
    const float* bo  = (const float*)d_in[8];
    const float* gm  = (const float*)d_in[9];
    const float* bt  = (const float*)d_in[10];
    const float* rm  = (const float*)d_in[11];
    const float* rv  = (const float*)d_in[12];
    float* out = (float*)d_out;

    // raise dynamic smem cap for flash3 (69,632 B); host attr set, capture-safe
    cudaFuncSetAttribute(flash3_kernel,
                         cudaFuncAttributeMaxDynamicSharedMemorySize,
                         F3_SMEM_BYTES);

    // Side stream + fork/join events for overlap of flash3 (head 3) with the
    // heads-0-2 chain. Created per call and intentionally leaked: no device
    // memory is allocated, and destroying a stream that participates in an
    // active capture is illegal. kernel_launch runs only a handful of times.
    cudaStream_t side;
    cudaStreamCreateWithFlags(&side, cudaStreamNonBlocking);
    cudaEvent_t evF, evJ;
    cudaEventCreateWithFlags(&evF, cudaEventDisableTiming);
    cudaEventCreateWithFlags(&evJ, cudaEventDisableTiming);

    qkv_kernel<<<dim3(64, 4, 4), 256>>>(x, Wq, bq, Wk, bk, Wv, bv);

    // fork: flash3 on side stream, dependent on qkv
    cudaEventRecord(evF, 0);
    cudaStreamWaitEvent(side, evF, 0);
    flash3_kernel<<<256, 256, F3_SMEM_BYTES, side>>>();

    // heads 0-2 chain on main stream (independent of flash3; disjoint g_attn)
    scores_kernel<<<1092, 256>>>();
    softmax_kernel<<<5376, 256>>>();
    av_kernel<<<768, 256>>>();

    // join: conv needs both g_attn halves
    cudaEventRecord(evJ, side);
    cudaStreamWaitEvent((cudaStream_t)0, evJ, 0);
    conv_bn_kernel<<<dim3(32, 4, 4), 256>>>(Wo, bo, gm, bt, rm, rv, out);
}